// round 15
// baseline (speedup 1.0000x reference)
#include <cuda_runtime.h>

// Problem constants
#define NN 262144
#define DD 128
#define KK 256
#define LL 4
#define TM 32           // rows per CTA
#define NTHREADS 512    // 16 warps, 4 per SMSP
#define KP 132          // padded k-row stride: %4==0 -> LDS.128 aligned & conflict-free

// Output layout: (qhard[N,D], qsoft[N,D], soft_dist, hard_dist, joint_center, error, hard_code[N,L])
#define QH_OFF   0L
#define QS_OFF   ((long)NN * DD)
#define SC_OFF   (2L * NN * DD)
#define CODE_OFF (2L * NN * DD + 4)

#define SMEM_FLOATS (KK*KP + 3*TM*DD + TM*KK + KK + 64)
#define SMEM_BYTES  (SMEM_FLOATS*4 + TM*LL*4)

typedef unsigned long long u64;

__device__ __forceinline__ u64 fma2(u64 a, u64 b, u64 c) {
    u64 d;
    asm("fma.rn.f32x2 %0, %1, %2, %3;" : "=l"(d) : "l"(a), "l"(b), "l"(c));
    return d;
}
__device__ __forceinline__ u64 pack2(float x, float y) {
    u64 d;
    asm("mov.b64 %0, {%1, %2};" : "=l"(d) : "f"(x), "f"(y));
    return d;
}
__device__ __forceinline__ float2 unpack2(u64 v) {
    float2 f;
    asm("mov.b64 {%0, %1}, %2;" : "=f"(f.x), "=f"(f.y) : "l"(v));
    return f;
}

__global__ void rvq_zero_scalars(float* out) {
    if (threadIdx.x < 4) out[SC_OFF + threadIdx.x] = 0.0f;
}

__global__ __launch_bounds__(NTHREADS, 1)
void rvq_kernel(const float* __restrict__ x_g,
                const float* __restrict__ cb_g,
                float* __restrict__ out) {
    extern __shared__ float sm[];
    float* sC   = sm;                       // [KK][KP]
    float* sR   = sC + KK*KP;               // residual [TM][DD]
    float* sX   = sR + TM*DD;               // original x [TM][DD]
    float* sQ   = sX + TM*DD;               // qsoft accum [TM][DD]
    float* sP   = sQ + TM*DD;               // dots -> probs [TM][KK]; later scratch x2
    float* sCC  = sP + TM*KK;               // code norms [KK]
    float* sRed = sCC + KK;                 // 4 x 16 warp partials
    int*   sCode= (int*)(sRed + 64);        // [TM][LL]

    const int tid  = threadIdx.x;
    const int lane = tid & 31;
    const int w    = tid >> 5;
    const long rowBase = (long)blockIdx.x * TM;

    // GEMM1 roles: 8-row group x 64-k quarter (disjoint sP columns -> no reduce)
    const int g1 = w >> 2;        // rows g1*8 .. +7
    const int q1 = w & 3;         // k in [q1*64, q1*64+64); lane owns k0, k0+32
    // GEMM2 roles: 8-row group x 64-k quarter, lane owns d-block 4*lane..4*lane+3
    const int g2 = w >> 2;        // rows g2*8 .. +7
    const int q2 = w & 3;         // k in [q2*64, q2*64+64)

    // ---- load tile (float4): residual = x, qsoft = 0 ----
    {
        const float4* xg4 = (const float4*)(x_g + rowBase*DD);
        float4* r4 = (float4*)sR; float4* x4 = (float4*)sX; float4* q4 = (float4*)sQ;
        const float4 z4 = make_float4(0.f, 0.f, 0.f, 0.f);
        for (int i = tid; i < (TM*DD)/4; i += NTHREADS) {
            float4 v = xg4[i];
            r4[i] = v; x4[i] = v; q4[i] = z4;
        }
    }
    __syncthreads();

    // owner rows for softmax/residual/distances: 2 per warp
    float* Rw = sR + (w*2)*DD;
    float* Xw = sX + (w*2)*DD;
    float* Qw = sQ + (w*2)*DD;

    // ---- initial rr = ||residual_row||^2 (identical arithmetic to R13) ----
    float rr[2];
    #pragma unroll
    for (int r = 0; r < 2; r++) {
        float4 v = *(const float4*)(Rw + r*DD + 4*lane);
        float s = v.x*v.x + v.y*v.y + v.z*v.z + v.w*v.w;
        #pragma unroll
        for (int o = 16; o > 0; o >>= 1) s += __shfl_xor_sync(0xffffffffu, s, o);
        rr[r] = s;
    }

    float softAcc = 0.0f, hardAcc = 0.0f, errAcc = 0.0f;

    for (int level = 0; level < LL; level++) {
        // ---- stage codebook into smem [k][KP] (LDG.128 -> STS.128), cc fused ----
        // iteration j: warp w handles code k = w + 16*j fully (lane owns d 4*lane..+3)
        {
            const float4* cbl4 = (const float4*)(cb_g + (long)level * KK * DD);
            #pragma unroll
            for (int j = 0; j < 16; j++) {
                int i = tid + NTHREADS*j;            // < 8192
                float4 v = cbl4[i];
                int k = i >> 5;                      // == w + 16*j (uniform in warp)
                int d = (i & 31) << 2;               // == 4*lane
                *(float4*)(sC + k*KP + d) = v;       // STS.128, conflict-free
                float s = v.x*v.x + v.y*v.y + v.z*v.z + v.w*v.w;
                #pragma unroll
                for (int o = 16; o > 0; o >>= 1) s += __shfl_xor_sync(0xffffffffu, s, o);
                if (lane == 0) sCC[k] = s;           // cc[k] for free
            }
        }
        __syncthreads();                                      // (b)

        // ---- GEMM1: warp computes dot[8 rows][2 k per lane] over its k-quarter ----
        {
            u64 acc[8][2];
            #pragma unroll
            for (int r = 0; r < 8; r++) { acc[r][0] = 0ull; acc[r][1] = 0ull; }

            const float* Rg  = sR + (g1*8)*DD;
            const float* Ck0 = sC + (q1*64 + lane)*KP;
            const float* Ck1 = Ck0 + 32*KP;
            #pragma unroll 2
            for (int d = 0; d < DD; d += 4) {
                ulonglong2 C0 = *(const ulonglong2*)(Ck0 + d);  // (d,d+1),(d+2,d+3)
                ulonglong2 C1 = *(const ulonglong2*)(Ck1 + d);
                #pragma unroll
                for (int r = 0; r < 8; r++) {
                    ulonglong2 R = *(const ulonglong2*)(Rg + r*DD + d);  // broadcast
                    acc[r][0] = fma2(R.x, C0.x, acc[r][0]);
                    acc[r][0] = fma2(R.y, C0.y, acc[r][0]);
                    acc[r][1] = fma2(R.x, C1.x, acc[r][1]);
                    acc[r][1] = fma2(R.y, C1.y, acc[r][1]);
                }
            }
            #pragma unroll
            for (int r = 0; r < 8; r++) {
                float2 f0 = unpack2(acc[r][0]);
                float2 f1 = unpack2(acc[r][1]);
                float* row = sP + (g1*8 + r)*KK + q1*64 + lane;
                row[0]  = f0.x + f0.y;
                row[32] = f1.x + f1.y;
            }
        }
        __syncthreads();                                      // (d)

        // ---- softmax + argmin + residual update (owner warp: rows w*2, w*2+1) ----
        float hardLevel = 0.0f;
        #pragma unroll
        for (int r = 0; r < 2; r++) {
            float* Prow = sP + (w*2 + r)*KK;
            float d2v[8];
            float mx = -1e30f;
            #pragma unroll
            for (int j = 0; j < 8; j++) {
                float dot = Prow[lane + 32*j];
                float t   = __fadd_rn(rr[r], sCC[lane + 32*j]);
                float d2  = __fmaf_rn(-2.0f, dot, t);
                d2v[j] = d2;
                mx = fmaxf(mx, d2);
            }
            #pragma unroll
            for (int o = 16; o > 0; o >>= 1) mx = fmaxf(mx, __shfl_xor_sync(0xffffffffu, mx, o));

            float bestv = 1e30f; int bestk = KK;
            #pragma unroll
            for (int j = 0; j < 8; j++) {
                float nv = __fdiv_rn(d2v[j], mx);             // IEEE div like the reference
                d2v[j] = nv;
                int k = lane + 32*j;
                if (nv < bestv || (nv == bestv && k < bestk)) { bestv = nv; bestk = k; }
            }
            #pragma unroll
            for (int o = 16; o > 0; o >>= 1) {
                float ov = __shfl_xor_sync(0xffffffffu, bestv, o);
                int   ok = __shfl_xor_sync(0xffffffffu, bestk, o);
                if (ov < bestv || (ov == bestv && ok < bestk)) { bestv = ov; bestk = ok; }
            }

            float z = 0.0f;
            #pragma unroll
            for (int j = 0; j < 8; j++) {
                float e = __expf(bestv - d2v[j]);
                d2v[j] = e;
                z += e;
            }
            #pragma unroll
            for (int o = 16; o > 0; o >>= 1) z += __shfl_xor_sync(0xffffffffu, z, o);
            float invz = 1.0f / z;
            #pragma unroll
            for (int j = 0; j < 8; j++)
                Prow[lane + 32*j] = d2v[j] * invz;            // normalized probs

            if (lane == 0) sCode[(w*2 + r)*LL + level] = bestk;

            // residual -= codes[bestk]; rr update; hard-dist partial
            const float* crow = sC + bestk*KP;
            float s = 0.0f;
            #pragma unroll
            for (int i = 0; i < 2; i++) {
                int d = 64*i + 2*lane;
                float2 rv = *(float2*)(Rw + r*DD + d);
                float2 cv = *(const float2*)(crow + d);
                rv.x -= cv.x; rv.y -= cv.y;
                *(float2*)(Rw + r*DD + d) = rv;
                s += rv.x*rv.x + rv.y*rv.y;
            }
            #pragma unroll
            for (int o = 16; o > 0; o >>= 1) s += __shfl_xor_sync(0xffffffffu, s, o);
            rr[r] = s;
            hardLevel += s;
        }
        hardAcc += hardLevel;
        if (level == LL - 1) errAcc = hardLevel;
        __syncthreads();                                      // (e) probs + residual ready

        // ---- GEMM2: warp computes partial qsoft[8 rows] over its k-quarter ----
        // lane owns d-block 4*lane..4*lane+3 ; C via single LDS.128 per k
        u64 a2[8][2];
        #pragma unroll
        for (int r = 0; r < 8; r++) { a2[r][0] = 0ull; a2[r][1] = 0ull; }
        {
            const float* Pg    = sP + (g2*8)*KK + q2*64;
            const float* Cbase = sC + (q2*64)*KP + 4*lane;
            #pragma unroll 1
            for (int k = 0; k < 64; k += 4) {
                float pr[8][4];
                #pragma unroll
                for (int r = 0; r < 8; r++) {
                    float4 p = *(const float4*)(Pg + r*KK + k);   // broadcast
                    pr[r][0] = p.x; pr[r][1] = p.y; pr[r][2] = p.z; pr[r][3] = p.w;
                }
                #pragma unroll
                for (int kk = 0; kk < 4; kk++) {
                    ulonglong2 C = *(const ulonglong2*)(Cbase + (k + kk)*KP);  // LDS.128
                    #pragma unroll
                    for (int r = 0; r < 8; r++) {
                        u64 pp = pack2(pr[r][kk], pr[r][kk]);
                        a2[r][0] = fma2(pp, C.x, a2[r][0]);
                        a2[r][1] = fma2(pp, C.y, a2[r][1]);
                    }
                }
            }
        }
        __syncthreads();                                      // (f) done reading sP/sC

        // ---- 2-stage cross-warp reduction of GEMM2 partials (scratch aliases sP) ----
        float* scr0 = sP;            // [32][128]
        float* scr1 = sP + TM*DD;    // [32][128]
        if (q2 == 1 || q2 == 3) {
            float* dst = (q2 == 1 ? scr0 : scr1) + (g2*8)*DD + 4*lane;
            #pragma unroll
            for (int r = 0; r < 8; r++) {
                float2 f0 = unpack2(a2[r][0]);
                float2 f1 = unpack2(a2[r][1]);
                *(float4*)(dst + r*DD) = make_float4(f0.x, f0.y, f1.x, f1.y);  // STS.128
            }
        }
        __syncthreads();                                      // (g)
        if (q2 == 0 || q2 == 2) {
            float* base = (q2 == 0 ? scr0 : scr1) + (g2*8)*DD + 4*lane;
            #pragma unroll
            for (int r = 0; r < 8; r++) {
                float4 sv = *(const float4*)(base + r*DD);
                float2 f0 = unpack2(a2[r][0]);
                float2 f1 = unpack2(a2[r][1]);
                f0.x += sv.x; f0.y += sv.y; f1.x += sv.z; f1.y += sv.w;
                a2[r][0] = pack2(f0.x, f0.y);
                a2[r][1] = pack2(f1.x, f1.y);
            }
            if (q2 == 2) {
                float* dst = scr1 + (g2*8)*DD + 4*lane;
                #pragma unroll
                for (int r = 0; r < 8; r++) {
                    float2 f0 = unpack2(a2[r][0]);
                    float2 f1 = unpack2(a2[r][1]);
                    *(float4*)(dst + r*DD) = make_float4(f0.x, f0.y, f1.x, f1.y);
                }
            }
        }
        __syncthreads();                                      // (g2)
        if (q2 == 0) {
            const float* src = scr1 + (g2*8)*DD + 4*lane;
            #pragma unroll
            for (int r = 0; r < 8; r++) {
                float* qrow = sQ + (g2*8 + r)*DD + 4*lane;
                float4 sv = *(const float4*)(src + r*DD);
                float4 qv = *(const float4*)qrow;
                float2 f0 = unpack2(a2[r][0]);
                float2 f1 = unpack2(a2[r][1]);
                qv.x += f0.x + sv.x;
                qv.y += f0.y + sv.y;
                qv.z += f1.x + sv.z;
                qv.w += f1.y + sv.w;
                *(float4*)qrow = qv;
            }
        }
        __syncthreads();                                      // (h) sQ ready

        // ---- soft-dist partial: ||x - qsoft||^2 (owner rows) ----
        float sp = 0.0f;
        #pragma unroll
        for (int r = 0; r < 2; r++) {
            float4 xv = *(const float4*)(Xw + r*DD + 4*lane);
            float4 qv = *(const float4*)(Qw + r*DD + 4*lane);
            float a0 = xv.x - qv.x, a1 = xv.y - qv.y, a2_ = xv.z - qv.z, a3 = xv.w - qv.w;
            sp += a0*a0 + a1*a1 + a2_*a2_ + a3*a3;
        }
        #pragma unroll
        for (int o = 16; o > 0; o >>= 1) sp += __shfl_xor_sync(0xffffffffu, sp, o);
        softAcc += sp;
    } // levels

    // ---- joint_center partial: (qsoft - qhard)^2, qhard = x - residual ----
    float jp = 0.0f;
    #pragma unroll
    for (int r = 0; r < 2; r++) {
        float4 xv = *(const float4*)(Xw + r*DD + 4*lane);
        float4 rv = *(const float4*)(Rw + r*DD + 4*lane);
        float4 qv = *(const float4*)(Qw + r*DD + 4*lane);
        float d0 = qv.x - (xv.x - rv.x);
        float d1 = qv.y - (xv.y - rv.y);
        float d2 = qv.z - (xv.z - rv.z);
        float d3 = qv.w - (xv.w - rv.w);
        jp += d0*d0 + d1*d1 + d2*d2 + d3*d3;
    }
    #pragma unroll
    for (int o = 16; o > 0; o >>= 1) jp += __shfl_xor_sync(0xffffffffu, jp, o);

    if (lane == 0) {
        sRed[w]      = softAcc;
        sRed[16 + w] = hardAcc;
        sRed[32 + w] = errAcc;
        sRed[48 + w] = jp;
    }
    __syncthreads();
    if (tid == 0) {
        float s = 0, h = 0, e = 0, j = 0;
        for (int i = 0; i < 16; i++) { s += sRed[i]; h += sRed[16+i]; e += sRed[32+i]; j += sRed[48+i]; }
        atomicAdd(out + SC_OFF + 0, s / (float)NN);                 // soft_dist
        atomicAdd(out + SC_OFF + 1, h / (float)NN);                 // hard_dist
        atomicAdd(out + SC_OFF + 2, j / ((float)NN * (float)DD));   // joint_center
        atomicAdd(out + SC_OFF + 3, e / (float)NN);                 // error
    }

    // ---- write qhard, qsoft (float4), hard_code ----
    {
        const float4* x4 = (const float4*)sX;
        const float4* r4 = (const float4*)sR;
        const float4* q4 = (const float4*)sQ;
        float4* qh4 = (float4*)(out + QH_OFF + rowBase*DD);
        float4* qs4 = (float4*)(out + QS_OFF + rowBase*DD);
        for (int i = tid; i < (TM*DD)/4; i += NTHREADS) {
            float4 xv = x4[i], rv = r4[i];
            qh4[i] = make_float4(xv.x - rv.x, xv.y - rv.y, xv.z - rv.z, xv.w - rv.w);
            qs4[i] = q4[i];
        }
    }
    for (int i = tid; i < TM*LL; i += NTHREADS)
        out[CODE_OFF + rowBase*LL + i] = (float)sCode[i];
}

extern "C" void kernel_launch(void* const* d_in, const int* in_sizes, int n_in,
                              void* d_out, int out_size) {
    (void)in_sizes; (void)n_in; (void)out_size;
    const float* x  = (const float*)d_in[0];
    const float* cb = (const float*)d_in[1];
    float* out = (float*)d_out;

    cudaFuncSetAttribute(rvq_kernel, cudaFuncAttributeMaxDynamicSharedMemorySize, SMEM_BYTES);

    rvq_zero_scalars<<<1, 32>>>(out);
    rvq_kernel<<<NN/TM, NTHREADS, SMEM_BYTES>>>(x, cb, out);
}

// round 16
// speedup vs baseline: 1.1644x; 1.1644x over previous
#include <cuda_runtime.h>
#include <cstdint>

// Problem constants
#define NN 262144
#define DD 128
#define KK 256
#define LL 4
#define TM 32           // rows per CTA
#define NTHREADS 512    // 16 warps, 4 per SMSP
#define KP 132          // padded k-row stride for sC (LDS.128 aligned, conflict-free)
#define PSTR 260        // padded row stride for sP (mma A-frag conflict-free: 260%32==4)

// Output layout: (qhard[N,D], qsoft[N,D], soft_dist, hard_dist, joint_center, error, hard_code[N,L])
#define QH_OFF   0L
#define QS_OFF   ((long)NN * DD)
#define SC_OFF   (2L * NN * DD)
#define CODE_OFF (2L * NN * DD + 4)

#define SMEM_FLOATS (KK*KP + 3*TM*DD + TM*PSTR + KK + 64)
#define SMEM_BYTES  (SMEM_FLOATS*4 + TM*LL*4)

typedef unsigned long long u64;

__device__ __forceinline__ u64 fma2(u64 a, u64 b, u64 c) {
    u64 d;
    asm("fma.rn.f32x2 %0, %1, %2, %3;" : "=l"(d) : "l"(a), "l"(b), "l"(c));
    return d;
}
__device__ __forceinline__ float2 unpack2(u64 v) {
    float2 f;
    asm("mov.b64 {%0, %1}, %2;" : "=f"(f.x), "=f"(f.y) : "l"(v));
    return f;
}
__device__ __forceinline__ uint32_t cvt_tf32(float f) {
    uint32_t u;
    asm("cvt.rna.tf32.f32 %0, %1;" : "=r"(u) : "f"(f));
    return u;
}
// D(16x8,f32) += A(16x8,tf32,row) * B(8x8,tf32,col)
__device__ __forceinline__ void mma_tf32(float* d,
                                         uint32_t a0, uint32_t a1, uint32_t a2, uint32_t a3,
                                         uint32_t b0, uint32_t b1) {
    asm volatile(
        "mma.sync.aligned.m16n8k8.row.col.f32.tf32.tf32.f32 "
        "{%0,%1,%2,%3}, {%4,%5,%6,%7}, {%8,%9}, {%0,%1,%2,%3};\n"
        : "+f"(d[0]), "+f"(d[1]), "+f"(d[2]), "+f"(d[3])
        : "r"(a0), "r"(a1), "r"(a2), "r"(a3), "r"(b0), "r"(b1));
}

__global__ void rvq_zero_scalars(float* out) {
    if (threadIdx.x < 4) out[SC_OFF + threadIdx.x] = 0.0f;
}

__global__ __launch_bounds__(NTHREADS, 1)
void rvq_kernel(const float* __restrict__ x_g,
                const float* __restrict__ cb_g,
                float* __restrict__ out) {
    extern __shared__ float sm[];
    float* sC   = sm;                       // [KK][KP]
    float* sR   = sC + KK*KP;               // residual [TM][DD]
    float* sX   = sR + TM*DD;               // original x [TM][DD]
    float* sQ   = sX + TM*DD;               // qsoft accum [TM][DD]
    float* sP   = sQ + TM*DD;               // dots -> probs [TM][PSTR]
    float* sCC  = sP + TM*PSTR;             // code norms [KK]
    float* sRed = sCC + KK;                 // 4 x 16 warp partials
    int*   sCode= (int*)(sRed + 64);        // [TM][LL]

    const int tid  = threadIdx.x;
    const int lane = tid & 31;
    const int w    = tid >> 5;
    const long rowBase = (long)blockIdx.x * TM;

    // GEMM1 roles: 8-row group x 64-k quarter (disjoint sP columns -> no reduce)
    const int g1 = w >> 2;        // rows g1*8 .. +7
    const int q1 = w & 3;         // k in [q1*64, q1*64+64); lane owns k0, k0+32
    // GEMM2 (mma.sync) roles: m-half x n-group of 16 cols; full K per warp
    const int mh = w & 1;         // rows mh*16 .. +15
    const int ng = w >> 1;        // cols ng*16 .. +15
    const int grp = lane >> 2;    // 0..7
    const int qd  = lane & 3;     // 0..3

    // ---- load tile (float4): residual = x, qsoft = 0 ----
    {
        const float4* xg4 = (const float4*)(x_g + rowBase*DD);
        float4* r4 = (float4*)sR; float4* x4 = (float4*)sX; float4* q4 = (float4*)sQ;
        const float4 z4 = make_float4(0.f, 0.f, 0.f, 0.f);
        for (int i = tid; i < (TM*DD)/4; i += NTHREADS) {
            float4 v = xg4[i];
            r4[i] = v; x4[i] = v; q4[i] = z4;
        }
    }
    __syncthreads();

    // owner rows for softmax/residual/distances: 2 per warp
    float* Rw = sR + (w*2)*DD;
    float* Xw = sX + (w*2)*DD;
    float* Qw = sQ + (w*2)*DD;

    // ---- initial rr = ||residual_row||^2 ----
    float rr[2];
    #pragma unroll
    for (int r = 0; r < 2; r++) {
        float4 v = *(const float4*)(Rw + r*DD + 4*lane);
        float s = v.x*v.x + v.y*v.y + v.z*v.z + v.w*v.w;
        #pragma unroll
        for (int o = 16; o > 0; o >>= 1) s += __shfl_xor_sync(0xffffffffu, s, o);
        rr[r] = s;
    }

    float softAcc = 0.0f, hardAcc = 0.0f, errAcc = 0.0f;

    for (int level = 0; level < LL; level++) {
        // ---- stage codebook into smem [k][KP] (LDG.128 -> STS.128), cc fused ----
        {
            const float4* cbl4 = (const float4*)(cb_g + (long)level * KK * DD);
            #pragma unroll
            for (int j = 0; j < 16; j++) {
                int i = tid + NTHREADS*j;            // < 8192
                float4 v = cbl4[i];
                int k = i >> 5;                      // uniform in warp
                int d = (i & 31) << 2;               // == 4*lane
                *(float4*)(sC + k*KP + d) = v;       // STS.128, conflict-free
                float s = v.x*v.x + v.y*v.y + v.z*v.z + v.w*v.w;
                #pragma unroll
                for (int o = 16; o > 0; o >>= 1) s += __shfl_xor_sync(0xffffffffu, s, o);
                if (lane == 0) sCC[k] = s;
            }
        }
        __syncthreads();                                      // (b)

        // ---- GEMM1 (fp32 f32x2, fidelity-critical): dot[8 rows][2 k/lane] ----
        {
            u64 acc[8][2];
            #pragma unroll
            for (int r = 0; r < 8; r++) { acc[r][0] = 0ull; acc[r][1] = 0ull; }

            const float* Rg  = sR + (g1*8)*DD;
            const float* Ck0 = sC + (q1*64 + lane)*KP;
            const float* Ck1 = Ck0 + 32*KP;
            #pragma unroll 2
            for (int d = 0; d < DD; d += 4) {
                ulonglong2 C0 = *(const ulonglong2*)(Ck0 + d);
                ulonglong2 C1 = *(const ulonglong2*)(Ck1 + d);
                #pragma unroll
                for (int r = 0; r < 8; r++) {
                    ulonglong2 R = *(const ulonglong2*)(Rg + r*DD + d);  // broadcast
                    acc[r][0] = fma2(R.x, C0.x, acc[r][0]);
                    acc[r][0] = fma2(R.y, C0.y, acc[r][0]);
                    acc[r][1] = fma2(R.x, C1.x, acc[r][1]);
                    acc[r][1] = fma2(R.y, C1.y, acc[r][1]);
                }
            }
            #pragma unroll
            for (int r = 0; r < 8; r++) {
                float2 f0 = unpack2(acc[r][0]);
                float2 f1 = unpack2(acc[r][1]);
                float* row = sP + (g1*8 + r)*PSTR + q1*64 + lane;
                row[0]  = f0.x + f0.y;
                row[32] = f1.x + f1.y;
            }
        }
        __syncthreads();                                      // (d)

        // ---- softmax + argmin + residual update (owner warp: rows w*2, w*2+1) ----
        float hardLevel = 0.0f;
        #pragma unroll
        for (int r = 0; r < 2; r++) {
            float* Prow = sP + (w*2 + r)*PSTR;
            float d2v[8];
            float mx = -1e30f;
            #pragma unroll
            for (int j = 0; j < 8; j++) {
                float dot = Prow[lane + 32*j];
                float t   = __fadd_rn(rr[r], sCC[lane + 32*j]);
                float d2  = __fmaf_rn(-2.0f, dot, t);
                d2v[j] = d2;
                mx = fmaxf(mx, d2);
            }
            #pragma unroll
            for (int o = 16; o > 0; o >>= 1) mx = fmaxf(mx, __shfl_xor_sync(0xffffffffu, mx, o));

            float bestv = 1e30f; int bestk = KK;
            #pragma unroll
            for (int j = 0; j < 8; j++) {
                float nv = __fdiv_rn(d2v[j], mx);             // IEEE div like the reference
                d2v[j] = nv;
                int k = lane + 32*j;
                if (nv < bestv || (nv == bestv && k < bestk)) { bestv = nv; bestk = k; }
            }
            #pragma unroll
            for (int o = 16; o > 0; o >>= 1) {
                float ov = __shfl_xor_sync(0xffffffffu, bestv, o);
                int   ok = __shfl_xor_sync(0xffffffffu, bestk, o);
                if (ov < bestv || (ov == bestv && ok < bestk)) { bestv = ov; bestk = ok; }
            }

            float z = 0.0f;
            #pragma unroll
            for (int j = 0; j < 8; j++) {
                float e = __expf(bestv - d2v[j]);
                d2v[j] = e;
                z += e;
            }
            #pragma unroll
            for (int o = 16; o > 0; o >>= 1) z += __shfl_xor_sync(0xffffffffu, z, o);
            float invz = 1.0f / z;
            #pragma unroll
            for (int j = 0; j < 8; j++)
                Prow[lane + 32*j] = d2v[j] * invz;            // normalized probs

            if (lane == 0) sCode[(w*2 + r)*LL + level] = bestk;

            // residual -= codes[bestk]; rr update; hard-dist partial
            const float* crow = sC + bestk*KP;
            float s = 0.0f;
            #pragma unroll
            for (int i = 0; i < 2; i++) {
                int d = 64*i + 2*lane;
                float2 rv = *(float2*)(Rw + r*DD + d);
                float2 cv = *(const float2*)(crow + d);
                rv.x -= cv.x; rv.y -= cv.y;
                *(float2*)(Rw + r*DD + d) = rv;
                s += rv.x*rv.x + rv.y*rv.y;
            }
            #pragma unroll
            for (int o = 16; o > 0; o >>= 1) s += __shfl_xor_sync(0xffffffffu, s, o);
            rr[r] = s;
            hardLevel += s;
        }
        hardAcc += hardLevel;
        if (level == LL - 1) errAcc = hardLevel;
        __syncthreads();                                      // (e) probs + residual ready

        // ---- GEMM2 via mma.sync tf32: qsoft[16x16 per warp] += P @ C ----
        {
            float dfr[2][4];
            #pragma unroll
            for (int nt = 0; nt < 2; nt++)
                #pragma unroll
                for (int i = 0; i < 4; i++) dfr[nt][i] = 0.0f;

            const float* A0 = sP + (mh*16 + grp)*PSTR + qd;   // row grp,   col qd
            const float* A1 = A0 + 8*PSTR;                    // row grp+8
            const int nbase = ng*16 + grp;
            #pragma unroll 4
            for (int kt = 0; kt < 32; kt++) {
                const int k0 = kt*8;
                uint32_t a0 = cvt_tf32(A0[k0]);
                uint32_t a1 = cvt_tf32(A1[k0]);
                uint32_t a2 = cvt_tf32(A0[k0 + 4]);
                uint32_t a3 = cvt_tf32(A1[k0 + 4]);
                const float* Bk0 = sC + (k0 + qd)*KP + nbase;
                uint32_t b00 = cvt_tf32(Bk0[0]);
                uint32_t b10 = cvt_tf32(Bk0[4*KP]);
                uint32_t b01 = cvt_tf32(Bk0[8]);
                uint32_t b11 = cvt_tf32(Bk0[4*KP + 8]);
                mma_tf32(dfr[0], a0, a1, a2, a3, b00, b10);
                mma_tf32(dfr[1], a0, a1, a2, a3, b01, b11);
            }
            // accumulate into sQ: warp owns rows mh*16..+15, cols ng*16..+15 (disjoint)
            #pragma unroll
            for (int nt = 0; nt < 2; nt++) {
                const int col = ng*16 + nt*8 + 2*qd;
                float* q0 = sQ + (mh*16 + grp)*DD + col;
                float* q1 = q0 + 8*DD;
                float2 v0 = *(float2*)q0;
                float2 v1 = *(float2*)q1;
                v0.x += dfr[nt][0]; v0.y += dfr[nt][1];
                v1.x += dfr[nt][2]; v1.y += dfr[nt][3];
                *(float2*)q0 = v0;
                *(float2*)q1 = v1;
            }
        }
        __syncthreads();                                      // (h) sQ ready, sP/sC free

        // ---- soft-dist partial: ||x - qsoft||^2 (owner rows) ----
        float sp = 0.0f;
        #pragma unroll
        for (int r = 0; r < 2; r++) {
            float4 xv = *(const float4*)(Xw + r*DD + 4*lane);
            float4 qv = *(const float4*)(Qw + r*DD + 4*lane);
            float a0 = xv.x - qv.x, a1 = xv.y - qv.y, a2_ = xv.z - qv.z, a3 = xv.w - qv.w;
            sp += a0*a0 + a1*a1 + a2_*a2_ + a3*a3;
        }
        #pragma unroll
        for (int o = 16; o > 0; o >>= 1) sp += __shfl_xor_sync(0xffffffffu, sp, o);
        softAcc += sp;
    } // levels

    // ---- joint_center partial: (qsoft - qhard)^2, qhard = x - residual ----
    float jp = 0.0f;
    #pragma unroll
    for (int r = 0; r < 2; r++) {
        float4 xv = *(const float4*)(Xw + r*DD + 4*lane);
        float4 rv = *(const float4*)(Rw + r*DD + 4*lane);
        float4 qv = *(const float4*)(Qw + r*DD + 4*lane);
        float d0 = qv.x - (xv.x - rv.x);
        float d1 = qv.y - (xv.y - rv.y);
        float d2 = qv.z - (xv.z - rv.z);
        float d3 = qv.w - (xv.w - rv.w);
        jp += d0*d0 + d1*d1 + d2*d2 + d3*d3;
    }
    #pragma unroll
    for (int o = 16; o > 0; o >>= 1) jp += __shfl_xor_sync(0xffffffffu, jp, o);

    if (lane == 0) {
        sRed[w]      = softAcc;
        sRed[16 + w] = hardAcc;
        sRed[32 + w] = errAcc;
        sRed[48 + w] = jp;
    }
    __syncthreads();
    if (tid == 0) {
        float s = 0, h = 0, e = 0, j = 0;
        for (int i = 0; i < 16; i++) { s += sRed[i]; h += sRed[16+i]; e += sRed[32+i]; j += sRed[48+i]; }
        atomicAdd(out + SC_OFF + 0, s / (float)NN);                 // soft_dist
        atomicAdd(out + SC_OFF + 1, h / (float)NN);                 // hard_dist
        atomicAdd(out + SC_OFF + 2, j / ((float)NN * (float)DD));   // joint_center
        atomicAdd(out + SC_OFF + 3, e / (float)NN);                 // error
    }

    // ---- write qhard, qsoft (float4), hard_code ----
    {
        const float4* x4 = (const float4*)sX;
        const float4* r4 = (const float4*)sR;
        const float4* q4 = (const float4*)sQ;
        float4* qh4 = (float4*)(out + QH_OFF + rowBase*DD);
        float4* qs4 = (float4*)(out + QS_OFF + rowBase*DD);
        for (int i = tid; i < (TM*DD)/4; i += NTHREADS) {
            float4 xv = x4[i], rv = r4[i];
            qh4[i] = make_float4(xv.x - rv.x, xv.y - rv.y, xv.z - rv.z, xv.w - rv.w);
            qs4[i] = q4[i];
        }
    }
    for (int i = tid; i < TM*LL; i += NTHREADS)
        out[CODE_OFF + rowBase*LL + i] = (float)sCode[i];
}

extern "C" void kernel_launch(void* const* d_in, const int* in_sizes, int n_in,
                              void* d_out, int out_size) {
    (void)in_sizes; (void)n_in; (void)out_size;
    const float* x  = (const float*)d_in[0];
    const float* cb = (const float*)d_in[1];
    float* out = (float*)d_out;

    cudaFuncSetAttribute(rvq_kernel, cudaFuncAttributeMaxDynamicSharedMemorySize, SMEM_BYTES);

    rvq_zero_scalars<<<1, 32>>>(out);
    rvq_kernel<<<NN/TM, NTHREADS, SMEM_BYTES>>>(x, cb, out);
}